// round 2
// baseline (speedup 1.0000x reference)
#include <cuda_runtime.h>
#include <cuda_bf16.h>
#include <math.h>

// ---------------- problem constants ----------------
// B=1024, H=512, half=256
// conv1: 2->64, 3x3, s1 p1, 32x32 -> 32x32
// conv2: 64->128, 3x3, s2 p1, 32x32 -> 16x16
// conv3: 128->256, 16x16 valid -> 1x1  (GEMM 1024x256x32768)
// GRU: x[1024,512] -> gi = x @ Wih^T, gh = h0 @ Whh^T, gates.

#define BATCH 1024
#define LEAK 0.01f

// ---------------- device scratch ----------------
__device__ float g_h1[1024 * 64 * 32 * 32];    // 256 MB
__device__ float g_h2[1024 * 128 * 16 * 16];   // 128 MB
__device__ float g_w2t[64 * 9 * 128];          // transposed conv2 weights [ic][k][oc]
__device__ float g_part[16 * 1024 * 256];      // conv3 split-K partials
__device__ float g_x[1024 * 512];              // GRU input (prevec | heightvec)
__device__ float g_gi[1024 * 1536];
__device__ float g_gh[1024 * 1536];

__device__ __forceinline__ float leaky(float v) { return v >= 0.f ? v : LEAK * v; }

// ---------------- conv1: 2->64 3x3 p1, + leaky ----------------
// grid 4096 (4 blocks per image), block 256, one output spatial position/thread.
__global__ void __launch_bounds__(256) conv1_kernel(const float* __restrict__ hm,
                                                    const float* __restrict__ w,
                                                    const float* __restrict__ bias) {
    int b = blockIdx.x >> 2;
    int p = ((blockIdx.x & 3) << 8) + threadIdx.x;   // 0..1023
    int oy = p >> 5, ox = p & 31;

    __shared__ float in_s[2048];          // 2x32x32
    __shared__ float w_s[64 * 20];        // 18 weights per oc, padded to 20 (f4 aligned)
    __shared__ float b_s[64];

    const float4* src = (const float4*)(hm + (size_t)b * 2048);
    float4* dst = (float4*)in_s;
    for (int i = threadIdx.x; i < 512; i += 256) dst[i] = src[i];
    for (int i = threadIdx.x; i < 64 * 20; i += 256) {
        int oc = i / 20, k = i % 20;
        w_s[i] = (k < 18) ? w[oc * 18 + k] : 0.f;
    }
    if (threadIdx.x < 64) b_s[threadIdx.x] = bias[threadIdx.x];
    __syncthreads();

    float v[18];
#pragma unroll
    for (int c = 0; c < 2; c++)
#pragma unroll
        for (int ky = 0; ky < 3; ky++)
#pragma unroll
            for (int kx = 0; kx < 3; kx++) {
                int iy = oy - 1 + ky, ix = ox - 1 + kx;
                float t = 0.f;
                if (iy >= 0 && iy < 32 && ix >= 0 && ix < 32) t = in_s[c * 1024 + iy * 32 + ix];
                v[c * 9 + ky * 3 + kx] = t;
            }

    float* out = g_h1 + (size_t)b * 65536 + p;
    for (int oc = 0; oc < 64; oc++) {
        const float4* wp = (const float4*)(w_s + oc * 20);
        float4 w0 = wp[0], w1 = wp[1], w2 = wp[2], w3 = wp[3];
        float2 w4 = *(const float2*)(w_s + oc * 20 + 16);
        float acc = b_s[oc];
        acc += v[0] * w0.x + v[1] * w0.y + v[2] * w0.z + v[3] * w0.w;
        acc += v[4] * w1.x + v[5] * w1.y + v[6] * w1.z + v[7] * w1.w;
        acc += v[8] * w2.x + v[9] * w2.y + v[10] * w2.z + v[11] * w2.w;
        acc += v[12] * w3.x + v[13] * w3.y + v[14] * w3.z + v[15] * w3.w;
        acc += v[16] * w4.x + v[17] * w4.y;
        out[oc * 1024] = leaky(acc);
    }
}

// ---------------- conv2 weight transpose: [oc][ic][k] -> [ic][k][oc] ----------------
__global__ void __launch_bounds__(256) w2t_kernel(const float* __restrict__ w) {
    int t = blockIdx.x * 256 + threadIdx.x;
    if (t >= 64 * 9 * 128) return;
    int ic = t / 1152;
    int rem = t - ic * 1152;
    int k = rem >> 7;
    int oc = rem & 127;
    g_w2t[t] = w[oc * 576 + ic * 9 + k];
}

// ---------------- conv2: 64->128 3x3 s2 p1, + leaky ----------------
// grid 2048 (image, oc-half), block 256. Thread tile: 8 oc x 8 spatial.
// warp = one 8-oc group, lane -> spatial: p = lane + 32*q (stores coalesce).
__global__ void __launch_bounds__(256, 2) conv2_kernel(const float* __restrict__ bias) {
    int b = blockIdx.x >> 1;
    int ocb = (blockIdx.x & 1) << 6;   // 0 or 64
    int tid = threadIdx.x;
    int lane = tid & 31, wrp = tid >> 5;
    int ox = lane & 15;
    int oy0 = lane >> 4;               // 0/1

    __shared__ float in_s[1024];       // one input channel 32x32
    __shared__ float w_s[576];         // [k][oc_local 64]

    float acc[8][8];
#pragma unroll
    for (int o = 0; o < 8; o++)
#pragma unroll
        for (int q = 0; q < 8; q++) acc[o][q] = 0.f;

    const float* inG = g_h1 + (size_t)b * 65536;

    for (int ic = 0; ic < 64; ic++) {
        __syncthreads();
        ((float4*)in_s)[tid] = ((const float4*)(inG + ic * 1024))[tid];
        for (int i = tid; i < 576; i += 256)
            w_s[i] = g_w2t[ic * 1152 + ((i >> 6) << 7) + ocb + (i & 63)];
        __syncthreads();

#pragma unroll
        for (int k = 0; k < 9; k++) {
            int ky = k / 3, kx = k - 3 * (k / 3);
            int ix = 2 * ox - 1 + kx;
            float vv[8];
#pragma unroll
            for (int q = 0; q < 8; q++) {
                int oy = oy0 + 2 * q;
                int iy = 2 * oy - 1 + ky;
                float t = 0.f;
                if (iy >= 0 && ix >= 0) t = in_s[iy * 32 + ix];  // iy<32, ix<32 always
                vv[q] = t;
            }
            float4 wa = *(const float4*)(w_s + k * 64 + wrp * 8);
            float4 wb = *(const float4*)(w_s + k * 64 + wrp * 8 + 4);
            float wr[8] = {wa.x, wa.y, wa.z, wa.w, wb.x, wb.y, wb.z, wb.w};
#pragma unroll
            for (int o = 0; o < 8; o++)
#pragma unroll
                for (int q = 0; q < 8; q++) acc[o][q] += wr[o] * vv[q];
        }
    }

    float* outG = g_h2 + (size_t)b * 32768;
#pragma unroll
    for (int o = 0; o < 8; o++) {
        int oc = ocb + wrp * 8 + o;
        float bz = bias[oc];
#pragma unroll
        for (int q = 0; q < 8; q++) {
            float r = acc[o][q] + bz;
            outG[oc * 256 + q * 32 + lane] = leaky(r);
        }
    }
}

// ---------------- generic GEMM: C[m][n] = sum_k A[m][k]*B[n][k] ----------------
// 64x64 tile per CTA, 256 threads, 4x4 per thread, kc=32.
// blockIdx.x -> m tile, .y -> n tile, .z -> k chunk. C += kz*cStride.
__global__ void __launch_bounds__(256) gemm_tn_kernel(const float* __restrict__ A,
                                                      const float* __restrict__ B,
                                                      float* __restrict__ C,
                                                      int lda, int ldb, int ldc,
                                                      int kLen, long long cStride) {
    __shared__ float As[32][68];
    __shared__ float Bs[32][68];
    int m0 = blockIdx.x * 64, n0 = blockIdx.y * 64;
    int kz = blockIdx.z;
    long long k0 = (long long)kz * kLen;
    int tid = threadIdx.x;
    int tx = tid & 15, ty = tid >> 4;

    float acc[4][4] = {};
    const float* Ap = A + (size_t)m0 * lda + k0;
    const float* Bp = B + (size_t)n0 * ldb + k0;

    for (int kk = 0; kk < kLen; kk += 32) {
#pragma unroll
        for (int h = 0; h < 2; h++) {
            int idx = tid + h * 256;       // 0..511
            int r = idx >> 3, c4 = idx & 7;
            float4 a = *(const float4*)(Ap + (size_t)r * lda + kk + c4 * 4);
            As[c4 * 4 + 0][r] = a.x; As[c4 * 4 + 1][r] = a.y;
            As[c4 * 4 + 2][r] = a.z; As[c4 * 4 + 3][r] = a.w;
            float4 bv = *(const float4*)(Bp + (size_t)r * ldb + kk + c4 * 4);
            Bs[c4 * 4 + 0][r] = bv.x; Bs[c4 * 4 + 1][r] = bv.y;
            Bs[c4 * 4 + 2][r] = bv.z; Bs[c4 * 4 + 3][r] = bv.w;
        }
        __syncthreads();
#pragma unroll
        for (int k2 = 0; k2 < 32; k2++) {
            float4 a4 = *(const float4*)&As[k2][tx * 4];
            float4 b4 = *(const float4*)&Bs[k2][ty * 4];
            float av[4] = {a4.x, a4.y, a4.z, a4.w};
            float bw[4] = {b4.x, b4.y, b4.z, b4.w};
#pragma unroll
            for (int i = 0; i < 4; i++)
#pragma unroll
                for (int j = 0; j < 4; j++) acc[i][j] += av[i] * bw[j];
        }
        __syncthreads();
    }

    float* Cw = C + (long long)kz * cStride;
#pragma unroll
    for (int i = 0; i < 4; i++)
#pragma unroll
        for (int j = 0; j < 4; j++)
            Cw[(size_t)(m0 + tx * 4 + i) * ldc + n0 + ty * 4 + j] = acc[i][j];
}

// ---------------- split-K reduce + conv3 bias/leaky + prebox -> g_x ----------------
__global__ void __launch_bounds__(256) build_x_kernel(const float* __restrict__ pre_box,
                                                      const float* __restrict__ pw,
                                                      const float* __restrict__ pb,
                                                      const float* __restrict__ c3b) {
    int t = blockIdx.x * 256 + threadIdx.x;   // 0 .. 1024*512-1
    int b = t >> 9, j = t & 511;
    float s;
    if (j < 256) {
        s = pb[j] + pre_box[b * 3] * pw[j * 3] + pre_box[b * 3 + 1] * pw[j * 3 + 1] +
            pre_box[b * 3 + 2] * pw[j * 3 + 2];
    } else {
        int n = j - 256;
        s = 0.f;
#pragma unroll
        for (int kz = 0; kz < 16; kz++) s += g_part[kz * 262144 + b * 256 + n];
        s += c3b[n];
        s = leaky(s);
    }
    g_x[t] = s;
}

// ---------------- GRU gates ----------------
__device__ __forceinline__ float sigmoid_t(float x) { return 0.5f + 0.5f * tanhf(0.5f * x); }

__global__ void __launch_bounds__(256) gates_kernel(const float* __restrict__ hh,
                                                    const float* __restrict__ bih,
                                                    const float* __restrict__ bhh,
                                                    float* __restrict__ out) {
    int t = blockIdx.x * 256 + threadIdx.x;   // 0 .. 1024*512-1
    int b = t >> 9, j = t & 511;
    size_t base = (size_t)b * 1536 + j;
    float ir = g_gi[base] + bih[j];
    float iz = g_gi[base + 512] + bih[512 + j];
    float inn = g_gi[base + 1024] + bih[1024 + j];
    float hr = g_gh[base] + bhh[j];
    float hz = g_gh[base + 512] + bhh[512 + j];
    float hn = g_gh[base + 1024] + bhh[1024 + j];
    float r = sigmoid_t(ir + hr);
    float z = sigmoid_t(iz + hz);
    float n = tanhf(inn + r * hn);
    float h0 = hh[t];
    float hnew = (1.f - z) * n + z * h0;
    out[t] = hnew;
    out[524288 + t] = hnew;   // new_hh
}

// ---------------- launch ----------------
extern "C" void kernel_launch(void* const* d_in, const int* in_sizes, int n_in,
                              void* d_out, int out_size) {
    (void)in_sizes; (void)n_in; (void)out_size;
    const float* pre_box = (const float*)d_in[0];
    const float* hm      = (const float*)d_in[1];
    const float* last_hh = (const float*)d_in[2];
    const float* pw      = (const float*)d_in[3];
    const float* pb      = (const float*)d_in[4];
    const float* c1w     = (const float*)d_in[5];
    const float* c1b     = (const float*)d_in[6];
    const float* c2w     = (const float*)d_in[7];
    const float* c2b     = (const float*)d_in[8];
    const float* c3w     = (const float*)d_in[9];
    const float* c3b     = (const float*)d_in[10];
    const float* wih     = (const float*)d_in[11];
    const float* whh     = (const float*)d_in[12];
    const float* bih     = (const float*)d_in[13];
    const float* bhh     = (const float*)d_in[14];
    float* out = (float*)d_out;

    float *p_h2, *p_part, *p_x, *p_gi, *p_gh;
    cudaGetSymbolAddress((void**)&p_h2, g_h2);
    cudaGetSymbolAddress((void**)&p_part, g_part);
    cudaGetSymbolAddress((void**)&p_x, g_x);
    cudaGetSymbolAddress((void**)&p_gi, g_gi);
    cudaGetSymbolAddress((void**)&p_gh, g_gh);

    conv1_kernel<<<4096, 256>>>(hm, c1w, c1b);
    w2t_kernel<<<288, 256>>>(c2w);
    conv2_kernel<<<2048, 256>>>(c2b);

    // conv3 as GEMM 1024x256x32768, split-K 16 chunks of 2048
    gemm_tn_kernel<<<dim3(16, 4, 16), 256>>>(p_h2, c3w, p_part,
                                             32768, 32768, 256, 2048, 262144LL);
    build_x_kernel<<<2048, 256>>>(pre_box, pw, pb, c3b);

    // GRU GEMMs: 1024x1536x512
    gemm_tn_kernel<<<dim3(16, 24, 1), 256>>>(p_x, wih, p_gi, 512, 512, 1536, 512, 0LL);
    gemm_tn_kernel<<<dim3(16, 24, 1), 256>>>(last_hh, whh, p_gh, 512, 512, 1536, 512, 0LL);

    gates_kernel<<<2048, 256>>>(last_hh, bih, bhh, out);
}

// round 5
// speedup vs baseline: 1.4178x; 1.4178x over previous
#include <cuda_runtime.h>
#include <math.h>
#include <stdint.h>

// B=1024, H=512. conv1 2->64 3x3 s1p1 (32x32), conv2 64->128 3x3 s2p1 (->16x16),
// conv3 128->256 16x16 valid (->1x1), GRU 512.
#define LEAK 0.01f

// ---------------- device scratch ----------------
__device__ float g_im[1024ull * 256 * 576];     // im2col for conv2 (~604MB)
__device__ float g_w2[128 * 576];               // conv2 weights [oc][tap*64+ic]
__device__ float g_h2n[1024ull * 256 * 128];    // conv2 out NHWC (b,pos,oc)
__device__ float g_c3wp[256ull * 32768];        // conv3 weights [n][p*128+oc]
__device__ float g_part[16ull * 1024 * 256];    // conv3 split-K partials
__device__ float g_x[1024 * 512];
__device__ float g_gi[1024 * 1536];
__device__ float g_gh[1024 * 1536];

__device__ __forceinline__ float leaky(float v) { return v >= 0.f ? v : LEAK * v; }

__device__ __forceinline__ uint32_t f2tf32(float x) {
    uint32_t r;
    asm("cvt.rna.tf32.f32 %0, %1;" : "=r"(r) : "f"(x));
    return r;
}

// ---------------- conv1 + fused im2col scatter ----------------
// grid 2048 = (image, y-half). Computes 17 rows x 32 x 64ch of conv1 output into
// smem stage, then writes 128 im2col rows (576 floats each, contiguous) coalesced.
__global__ void __launch_bounds__(256) conv1_kernel(const float* __restrict__ hm,
                                                    const float* __restrict__ w,
                                                    const float* __restrict__ bias) {
    extern __shared__ float sm[];
    float* in_s = sm;            // 2048
    float* w_s = sm + 2048;      // 64*20
    float* b_s = sm + 3328;      // 64
    float* stage = sm + 3392;    // 17*32*64 = 34816
    int tid = threadIdx.x;
    int b = blockIdx.x >> 1;
    int halfb = blockIdx.x & 1;
    int ystart = halfb ? 15 : -1;

    const float4* src = (const float4*)(hm + (size_t)b * 2048);
    for (int i = tid; i < 512; i += 256) ((float4*)in_s)[i] = src[i];
    for (int i = tid; i < 1280; i += 256) {
        int oc = i / 20, k = i - oc * 20;
        w_s[i] = (k < 18) ? w[oc * 18 + k] : 0.f;
    }
    if (tid < 64) b_s[tid] = bias[tid];
    __syncthreads();

    for (int p = tid; p < 544; p += 256) {
        int yl = p >> 5, x = p & 31;
        int y = ystart + yl;
        float* st = stage + (size_t)p * 64;
        if (y < 0) {
            for (int c = 0; c < 16; c++) ((float4*)st)[c] = make_float4(0, 0, 0, 0);
        } else {
            float v[18];
#pragma unroll
            for (int c = 0; c < 2; c++)
#pragma unroll
                for (int ky = 0; ky < 3; ky++)
#pragma unroll
                    for (int kx = 0; kx < 3; kx++) {
                        int yy = y - 1 + ky, xx = x - 1 + kx;
                        float t = 0.f;
                        if (yy >= 0 && yy < 32 && xx >= 0 && xx < 32) t = in_s[c * 1024 + yy * 32 + xx];
                        v[c * 9 + ky * 3 + kx] = t;
                    }
            for (int oc = 0; oc < 64; oc++) {
                const float4* wp = (const float4*)(w_s + oc * 20);
                float4 w0 = wp[0], w1 = wp[1], w2 = wp[2], w3 = wp[3];
                float2 w4 = *(const float2*)(w_s + oc * 20 + 16);
                float acc = b_s[oc];
                acc += v[0] * w0.x + v[1] * w0.y + v[2] * w0.z + v[3] * w0.w;
                acc += v[4] * w1.x + v[5] * w1.y + v[6] * w1.z + v[7] * w1.w;
                acc += v[8] * w2.x + v[9] * w2.y + v[10] * w2.z + v[11] * w2.w;
                acc += v[12] * w3.x + v[13] * w3.y + v[14] * w3.z + v[15] * w3.w;
                acc += v[16] * w4.x + v[17] * w4.y;
                st[oc] = leaky(acc);
            }
        }
    }
    __syncthreads();

    // write 128 im2col rows: row = oyl*16+ox, content [tap][64ch]
    float4* base = (float4*)(g_im + ((size_t)b * 256 + halfb * 128) * 576);
    for (int i = tid; i < 18432; i += 256) {
        int pos = i / 144;
        int rem = i - pos * 144;
        int oyl = pos >> 4, ox = pos & 15;
        int tap = rem >> 4, c4 = rem & 15;
        int ky = tap / 3, kx = tap - 3 * (tap / 3);
        int yl = 2 * oyl + ky;
        int x = 2 * ox - 1 + kx;
        float4 v = make_float4(0, 0, 0, 0);
        if (x >= 0) v = *(float4*)&stage[(size_t)(yl * 32 + x) * 64 + c4 * 4];
        base[i] = v;
    }
}

// ---------------- conv2 weight permute: [oc][ic][3][3] -> [oc][tap*64+ic] -----
__global__ void __launch_bounds__(256) w2p_kernel(const float* __restrict__ w) {
    int t = blockIdx.x * 256 + threadIdx.x;
    if (t >= 128 * 576) return;
    int oc = t / 576, k = t - oc * 576;
    int tap = k >> 6, ic = k & 63;
    g_w2[t] = w[oc * 576 + ic * 9 + tap];
}

// ---------------- conv3 weight transpose: [n][oc][p] -> [n][p*128+oc] ---------
__global__ void c3t_kernel(const float* __restrict__ w) {
    __shared__ float t[32][33];
    int n = blockIdx.z, oc0 = blockIdx.y * 32, p0 = blockIdx.x * 32;
    int tx = threadIdx.x, ty = threadIdx.y;
#pragma unroll
    for (int rr = 0; rr < 4; rr++)
        t[ty + rr * 8][tx] = w[(size_t)n * 32768 + (size_t)(oc0 + ty + rr * 8) * 256 + p0 + tx];
    __syncthreads();
#pragma unroll
    for (int rr = 0; rr < 4; rr++)
        g_c3wp[(size_t)n * 32768 + (size_t)(p0 + ty + rr * 8) * 128 + oc0 + tx] = t[tx][ty + rr * 8];
}

// ---------------- tf32 mma.sync GEMM: C[m][n] = sum_k A[m][k]*B[n][k] ---------
// CTA tile 128x64, 256 thr = 8 warps (4m x 2n), warp tile 32x32,
// mma.m16n8k8 tf32, K chunks of 32, smem stride-36 (conflict-free frags).
__global__ void __launch_bounds__(256) gemm_mma(const float* __restrict__ A,
                                                const float* __restrict__ B,
                                                float* __restrict__ C,
                                                int lda, int ldb, int ldc, int kLen,
                                                long long cStride,
                                                const float* __restrict__ bias, int act) {
    __shared__ float As[128 * 36];
    __shared__ float Bs[64 * 36];

    int tid = threadIdx.x;
    int lane = tid & 31, wid = tid >> 5;
    int wm = wid & 3, wn = wid >> 2;            // warp grid 4m x 2n
    int gid = lane >> 2, tc = lane & 3;
    int m0 = blockIdx.x << 7, n0 = blockIdx.y << 6;
    long long k0 = (long long)blockIdx.z * kLen;

    // load assignments
    int arow = tid >> 1, ahalf = tid & 1;       // A: 128 rows x 2 halves x 16 floats
    int brow = tid >> 2, bseg = tid & 3;        // B: 64 rows x 4 segs x 8 floats

    const float* Ap = A + (size_t)(m0 + arow) * lda + k0 + ahalf * 16;
    const float* Bp = B + (size_t)(n0 + brow) * ldb + k0 + bseg * 8;

    float c[2][4][4];
#pragma unroll
    for (int mt = 0; mt < 2; mt++)
#pragma unroll
        for (int nt = 0; nt < 4; nt++)
#pragma unroll
            for (int i = 0; i < 4; i++) c[mt][nt][i] = 0.f;

    int nc = kLen >> 5;
    float4 ra[4], rb[2];
#pragma unroll
    for (int j = 0; j < 4; j++) ra[j] = *(const float4*)(Ap + 4 * j);
#pragma unroll
    for (int j = 0; j < 2; j++) rb[j] = *(const float4*)(Bp + 4 * j);

    for (int ch = 0; ch < nc; ch++) {
        // STS with tf32 rounding
        uint32_t abase = arow * 36 + ahalf * 16;
#pragma unroll
        for (int j = 0; j < 4; j++) {
            float4 v = ra[j];
            uint32_t* d = (uint32_t*)&As[abase + 4 * j];
            d[0] = f2tf32(v.x); d[1] = f2tf32(v.y); d[2] = f2tf32(v.z); d[3] = f2tf32(v.w);
        }
        uint32_t bbase = brow * 36 + bseg * 8;
#pragma unroll
        for (int j = 0; j < 2; j++) {
            float4 v = rb[j];
            uint32_t* d = (uint32_t*)&Bs[bbase + 4 * j];
            d[0] = f2tf32(v.x); d[1] = f2tf32(v.y); d[2] = f2tf32(v.z); d[3] = f2tf32(v.w);
        }
        __syncthreads();

        if (ch + 1 < nc) {
            Ap += 32; Bp += 32;
#pragma unroll
            for (int j = 0; j < 4; j++) ra[j] = *(const float4*)(Ap + 4 * j);
#pragma unroll
            for (int j = 0; j < 2; j++) rb[j] = *(const float4*)(Bp + 4 * j);
        }

#pragma unroll
        for (int ks = 0; ks < 4; ks++) {
            uint32_t a[2][4], bq[4][2];
#pragma unroll
            for (int mt = 0; mt < 2; mt++) {
                const uint32_t* ap = (const uint32_t*)&As[(wm * 32 + mt * 16 + gid) * 36 + ks * 8 + tc];
                a[mt][0] = ap[0];
                a[mt][1] = ap[8 * 36];
                a[mt][2] = ap[4];
                a[mt][3] = ap[8 * 36 + 4];
            }
#pragma unroll
            for (int nt = 0; nt < 4; nt++) {
                const uint32_t* bp = (const uint32_t*)&Bs[(wn * 32 + nt * 8 + gid) * 36 + ks * 8 + tc];
                bq[nt][0] = bp[0];
                bq[nt][1] = bp[4];
            }
#pragma unroll
            for (int mt = 0; mt < 2; mt++)
#pragma unroll
                for (int nt = 0; nt < 4; nt++) {
                    asm volatile(
                        "mma.sync.aligned.m16n8k8.row.col.f32.tf32.tf32.f32 "
                        "{%0,%1,%2,%3}, {%4,%5,%6,%7}, {%8,%9}, {%0,%1,%2,%3};"
                        : "+f"(c[mt][nt][0]), "+f"(c[mt][nt][1]),
                          "+f"(c[mt][nt][2]), "+f"(c[mt][nt][3])
                        : "r"(a[mt][0]), "r"(a[mt][1]), "r"(a[mt][2]), "r"(a[mt][3]),
                          "r"(bq[nt][0]), "r"(bq[nt][1]));
                }
        }
        __syncthreads();
    }

    // epilogue
    float* Cz = C + (long long)blockIdx.z * cStride;
#pragma unroll
    for (int mt = 0; mt < 2; mt++) {
        int r0 = m0 + wm * 32 + mt * 16 + gid;
#pragma unroll
        for (int nt = 0; nt < 4; nt++) {
            int col = n0 + wn * 32 + nt * 8 + 2 * tc;
            float b0 = 0.f, b1 = 0.f;
            if (bias) { b0 = bias[col]; b1 = bias[col + 1]; }
            float v0 = c[mt][nt][0] + b0, v1 = c[mt][nt][1] + b1;
            float v2 = c[mt][nt][2] + b0, v3 = c[mt][nt][3] + b1;
            if (act) { v0 = leaky(v0); v1 = leaky(v1); v2 = leaky(v2); v3 = leaky(v3); }
            *(float2*)(Cz + (size_t)r0 * ldc + col) = make_float2(v0, v1);
            *(float2*)(Cz + (size_t)(r0 + 8) * ldc + col) = make_float2(v2, v3);
        }
    }
}

// ---------------- split-K reduce + conv3 bias/leaky + prebox -> g_x -----------
__global__ void __launch_bounds__(256) build_x_kernel(const float* __restrict__ pre_box,
                                                      const float* __restrict__ pw,
                                                      const float* __restrict__ pb,
                                                      const float* __restrict__ c3b) {
    int t = blockIdx.x * 256 + threadIdx.x;
    int b = t >> 9, j = t & 511;
    float s;
    if (j < 256) {
        s = pb[j] + pre_box[b * 3] * pw[j * 3] + pre_box[b * 3 + 1] * pw[j * 3 + 1] +
            pre_box[b * 3 + 2] * pw[j * 3 + 2];
    } else {
        int n = j - 256;
        s = 0.f;
#pragma unroll
        for (int kz = 0; kz < 16; kz++) s += g_part[kz * 262144 + b * 256 + n];
        s += c3b[n];
        s = leaky(s);
    }
    g_x[t] = s;
}

// ---------------- GRU gates ----------------
__device__ __forceinline__ float sigmoid_t(float x) { return 0.5f + 0.5f * tanhf(0.5f * x); }

__global__ void __launch_bounds__(256) gates_kernel(const float* __restrict__ hh,
                                                    const float* __restrict__ bih,
                                                    const float* __restrict__ bhh,
                                                    float* __restrict__ out) {
    int t = blockIdx.x * 256 + threadIdx.x;
    int b = t >> 9, j = t & 511;
    size_t base = (size_t)b * 1536 + j;
    float ir = g_gi[base] + bih[j];
    float iz = g_gi[base + 512] + bih[512 + j];
    float inn = g_gi[base + 1024] + bih[1024 + j];
    float hr = g_gh[base] + bhh[j];
    float hz = g_gh[base + 512] + bhh[512 + j];
    float hn = g_gh[base + 1024] + bhh[1024 + j];
    float r = sigmoid_t(ir + hr);
    float z = sigmoid_t(iz + hz);
    float n = tanhf(inn + r * hn);
    float h0 = hh[t];
    float hnew = (1.f - z) * n + z * h0;
    out[t] = hnew;
    out[524288 + t] = hnew;
}

// ---------------- launch ----------------
extern "C" void kernel_launch(void* const* d_in, const int* in_sizes, int n_in,
                              void* d_out, int out_size) {
    (void)in_sizes; (void)n_in; (void)out_size;
    const float* pre_box = (const float*)d_in[0];
    const float* hm      = (const float*)d_in[1];
    const float* last_hh = (const float*)d_in[2];
    const float* pw      = (const float*)d_in[3];
    const float* pb      = (const float*)d_in[4];
    const float* c1w     = (const float*)d_in[5];
    const float* c1b     = (const float*)d_in[6];
    const float* c2w     = (const float*)d_in[7];
    const float* c2b     = (const float*)d_in[8];
    const float* c3w     = (const float*)d_in[9];
    const float* c3b     = (const float*)d_in[10];
    const float* wih     = (const float*)d_in[11];
    const float* whh     = (const float*)d_in[12];
    const float* bih     = (const float*)d_in[13];
    const float* bhh     = (const float*)d_in[14];
    float* out = (float*)d_out;

    float *p_im, *p_w2, *p_h2n, *p_c3wp, *p_part, *p_x, *p_gi, *p_gh;
    cudaGetSymbolAddress((void**)&p_im, g_im);
    cudaGetSymbolAddress((void**)&p_w2, g_w2);
    cudaGetSymbolAddress((void**)&p_h2n, g_h2n);
    cudaGetSymbolAddress((void**)&p_c3wp, g_c3wp);
    cudaGetSymbolAddress((void**)&p_part, g_part);
    cudaGetSymbolAddress((void**)&p_x, g_x);
    cudaGetSymbolAddress((void**)&p_gi, g_gi);
    cudaGetSymbolAddress((void**)&p_gh, g_gh);

    cudaFuncSetAttribute(conv1_kernel, cudaFuncAttributeMaxDynamicSharedMemorySize, 152832);

    conv1_kernel<<<2048, 256, 152832>>>(hm, c1w, c1b);
    w2p_kernel<<<288, 256>>>(c2w);
    c3t_kernel<<<dim3(8, 4, 256), dim3(32, 8)>>>(c3w);

    // conv2: M=262144, N=128, K=576; bias + leaky fused, NHWC out
    gemm_mma<<<dim3(2048, 2, 1), 256>>>(p_im, p_w2, p_h2n, 576, 576, 128, 576, 0LL, c2b, 1);

    // conv3: M=1024, N=256, K=32768, split-K 16
    gemm_mma<<<dim3(8, 4, 16), 256>>>(p_h2n, p_c3wp, p_part, 32768, 32768, 256, 2048, 262144LL, (const float*)0, 0);
    build_x_kernel<<<2048, 256>>>(pre_box, pw, pb, c3b);

    // GRU GEMMs: M=1024, N=1536, K=512
    gemm_mma<<<dim3(8, 24, 1), 256>>>(p_x, wih, p_gi, 512, 512, 1536, 512, 0LL, (const float*)0, 0);
    gemm_mma<<<dim3(8, 24, 1), 256>>>(last_hh, whh, p_gh, 512, 512, 1536, 512, 0LL, (const float*)0, 0);

    gates_kernel<<<2048, 256>>>(last_hh, bih, bhh, out);
}

// round 6
// speedup vs baseline: 2.0011x; 1.4114x over previous
#include <cuda_runtime.h>
#include <math.h>
#include <stdint.h>

// B=1024, H=512. conv1 2->64 3x3 s1p1 (32x32), conv2 64->128 3x3 s2p1 (->16x16),
// conv3 128->256 16x16 valid (->1x1), GRU 512.
#define LEAK 0.01f

// ---------------- device scratch ----------------
// g_h1p: padded NHWC conv1 output [b][34][34][64]; border rows/cols are NEVER
// written by any kernel -> remain zero from static initialization (the zero
// padding conv2 needs).
__device__ float g_h1p[1024ull * 34 * 34 * 64];   // ~303MB
__device__ float g_w2[128 * 576];                 // conv2 weights [oc][tap*64+ic]
__device__ float g_h2n[1024ull * 256 * 128];      // conv2 out NHWC (b,pos,oc)
__device__ float g_c3wp[256ull * 32768];          // conv3 weights [n][p*128+oc]
__device__ float g_part[16ull * 1024 * 256];      // conv3 split-K partials
__device__ float g_x[1024 * 512];
__device__ float g_gi[1024 * 1536];
__device__ float g_gh[1024 * 1536];

__device__ __forceinline__ float leaky(float v) { return v >= 0.f ? v : LEAK * v; }

__device__ __forceinline__ uint32_t f2tf32(float x) {
    uint32_t r;
    asm("cvt.rna.tf32.f32 %0, %1;" : "=r"(r) : "f"(x));
    return r;
}
__device__ __forceinline__ void sts_tf32x4(float* dst, float4 v) {
    uint32_t* d = (uint32_t*)dst;
    d[0] = f2tf32(v.x); d[1] = f2tf32(v.y); d[2] = f2tf32(v.z); d[3] = f2tf32(v.w);
}

// ---------------- conv1: 2->64 3x3 p1 + leaky -> padded NHWC ----------------
// grid 4096 (4 blocks/image, 8 y-rows each), block 256 (thread = one (y,x)).
__global__ void __launch_bounds__(256) conv1_kernel(const float* __restrict__ hm,
                                                    const float* __restrict__ w,
                                                    const float* __restrict__ bias) {
    __shared__ float in_s[2048];
    __shared__ float w_s[64 * 20];
    __shared__ float b_s[64];
    int b = blockIdx.x >> 2, q = blockIdx.x & 3;
    int tid = threadIdx.x;
    int yl = tid >> 5, x = tid & 31;
    int y = q * 8 + yl;

    const float4* src = (const float4*)(hm + (size_t)b * 2048);
    for (int i = tid; i < 512; i += 256) ((float4*)in_s)[i] = src[i];
    for (int i = tid; i < 1280; i += 256) {
        int oc = i / 20, k = i - oc * 20;
        w_s[i] = (k < 18) ? w[oc * 18 + k] : 0.f;
    }
    if (tid < 64) b_s[tid] = bias[tid];
    __syncthreads();

    float v[18];
#pragma unroll
    for (int c = 0; c < 2; c++)
#pragma unroll
        for (int ky = 0; ky < 3; ky++)
#pragma unroll
            for (int kx = 0; kx < 3; kx++) {
                int yy = y - 1 + ky, xx = x - 1 + kx;
                float t = 0.f;
                if (yy >= 0 && yy < 32 && xx >= 0 && xx < 32) t = in_s[c * 1024 + yy * 32 + xx];
                v[c * 9 + ky * 3 + kx] = t;
            }

    float* dst = g_h1p + (((size_t)b * 34 + y + 1) * 34 + x + 1) * 64;
#pragma unroll 4
    for (int o4 = 0; o4 < 16; o4++) {
        float4 r;
        float* rp = (float*)&r;
#pragma unroll
        for (int u = 0; u < 4; u++) {
            int oc = o4 * 4 + u;
            const float4* wp = (const float4*)(w_s + oc * 20);
            float4 w0 = wp[0], w1 = wp[1], w2 = wp[2], w3 = wp[3];
            float2 w4 = *(const float2*)(w_s + oc * 20 + 16);
            float acc = b_s[oc];
            acc += v[0] * w0.x + v[1] * w0.y + v[2] * w0.z + v[3] * w0.w;
            acc += v[4] * w1.x + v[5] * w1.y + v[6] * w1.z + v[7] * w1.w;
            acc += v[8] * w2.x + v[9] * w2.y + v[10] * w2.z + v[11] * w2.w;
            acc += v[12] * w3.x + v[13] * w3.y + v[14] * w3.z + v[15] * w3.w;
            acc += v[16] * w4.x + v[17] * w4.y;
            rp[u] = leaky(acc);
        }
        ((float4*)dst)[o4] = r;
    }
}

// ---------------- conv2 weight permute: [oc][ic][3][3] -> [oc][tap*64+ic] -----
__global__ void __launch_bounds__(256) w2p_kernel(const float* __restrict__ w) {
    int t = blockIdx.x * 256 + threadIdx.x;
    if (t >= 128 * 576) return;
    int oc = t / 576, k = t - oc * 576;
    int tap = k >> 6, ic = k & 63;
    g_w2[t] = w[oc * 576 + ic * 9 + tap];
}

// ---------------- conv3 weight transpose: [n][oc][p] -> [n][p*128+oc] ---------
__global__ void c3t_kernel(const float* __restrict__ w) {
    __shared__ float t[32][33];
    int n = blockIdx.z, oc0 = blockIdx.y * 32, p0 = blockIdx.x * 32;
    int tx = threadIdx.x, ty = threadIdx.y;
#pragma unroll
    for (int rr = 0; rr < 4; rr++)
        t[ty + rr * 8][tx] = w[(size_t)n * 32768 + (size_t)(oc0 + ty + rr * 8) * 256 + p0 + tx];
    __syncthreads();
#pragma unroll
    for (int rr = 0; rr < 4; rr++)
        g_c3wp[(size_t)n * 32768 + (size_t)(p0 + ty + rr * 8) * 128 + oc0 + tx] = t[tx][ty + rr * 8];
}

// ================= shared MMA micro-kernel pieces =================
// CTA tile 128x64, 8 warps (4m x 2n), warp tile 32x32, m16n8k8 tf32.
// Smem rows stride 36 (conflict-free fragment LDS). Double buffered.
#define AS_STRIDE 4608   // 128*36
#define BS_STRIDE 2304   // 64*36
#define SMEM_BYTES ((2 * AS_STRIDE + 2 * BS_STRIDE) * 4)

struct MmaCtx {
    int lane, wm, wn, gid, tc;
    float c[2][4][4];
};

__device__ __forceinline__ void mma_chunk(const float* As, const float* Bs, MmaCtx& X) {
#pragma unroll
    for (int ks = 0; ks < 4; ks++) {
        uint32_t a[2][4], bq[4][2];
#pragma unroll
        for (int mt = 0; mt < 2; mt++) {
            const uint32_t* ap = (const uint32_t*)&As[(X.wm * 32 + mt * 16 + X.gid) * 36 + ks * 8 + X.tc];
            a[mt][0] = ap[0];
            a[mt][1] = ap[8 * 36];
            a[mt][2] = ap[4];
            a[mt][3] = ap[8 * 36 + 4];
        }
#pragma unroll
        for (int nt = 0; nt < 4; nt++) {
            const uint32_t* bp = (const uint32_t*)&Bs[(X.wn * 32 + nt * 8 + X.gid) * 36 + ks * 8 + X.tc];
            bq[nt][0] = bp[0];
            bq[nt][1] = bp[4];
        }
#pragma unroll
        for (int mt = 0; mt < 2; mt++)
#pragma unroll
            for (int nt = 0; nt < 4; nt++) {
                asm volatile(
                    "mma.sync.aligned.m16n8k8.row.col.f32.tf32.tf32.f32 "
                    "{%0,%1,%2,%3}, {%4,%5,%6,%7}, {%8,%9}, {%0,%1,%2,%3};"
                    : "+f"(X.c[mt][nt][0]), "+f"(X.c[mt][nt][1]),
                      "+f"(X.c[mt][nt][2]), "+f"(X.c[mt][nt][3])
                    : "r"(a[mt][0]), "r"(a[mt][1]), "r"(a[mt][2]), "r"(a[mt][3]),
                      "r"(bq[nt][0]), "r"(bq[nt][1]));
            }
    }
}

__device__ __forceinline__ void epilogue(MmaCtx& X, float* Cz, int m0, int n0, int ldc,
                                         const float* bias, int act) {
#pragma unroll
    for (int mt = 0; mt < 2; mt++) {
        int r0 = m0 + X.wm * 32 + mt * 16 + X.gid;
#pragma unroll
        for (int nt = 0; nt < 4; nt++) {
            int col = n0 + X.wn * 32 + nt * 8 + 2 * X.tc;
            float b0 = 0.f, b1 = 0.f;
            if (bias) { b0 = bias[col]; b1 = bias[col + 1]; }
            float v0 = X.c[mt][nt][0] + b0, v1 = X.c[mt][nt][1] + b1;
            float v2 = X.c[mt][nt][2] + b0, v3 = X.c[mt][nt][3] + b1;
            if (act) { v0 = leaky(v0); v1 = leaky(v1); v2 = leaky(v2); v3 = leaky(v3); }
            *(float2*)(Cz + (size_t)r0 * ldc + col) = make_float2(v0, v1);
            *(float2*)(Cz + (size_t)(r0 + 8) * ldc + col) = make_float2(v2, v3);
        }
    }
}

// ---------------- conv2 implicit GEMM: M=262144 N=128 K=576 ------------------
// grid (2048, 2): x = image*2 + y-half, y = oc-half. Reads g_h1p directly.
__global__ void __launch_bounds__(256) conv2_mma(const float* __restrict__ bias) {
    extern __shared__ float smem[];
    float* Asm = smem;
    float* Bsm = smem + 2 * AS_STRIDE;

    int tid = threadIdx.x;
    MmaCtx X;
    X.lane = tid & 31;
    int wid = tid >> 5;
    X.wm = wid & 3; X.wn = wid >> 2;
    X.gid = X.lane >> 2; X.tc = X.lane & 3;
#pragma unroll
    for (int mt = 0; mt < 2; mt++)
#pragma unroll
        for (int nt = 0; nt < 4; nt++)
#pragma unroll
            for (int i = 0; i < 4; i++) X.c[mt][nt][i] = 0.f;

    int bimg = blockIdx.x >> 1, halfb = blockIdx.x & 1;
    int n0 = blockIdx.y << 6;

    int arow = tid >> 1, ahalf = tid & 1;
    int brow = tid >> 2, bseg = tid & 3;
    int oyl = arow >> 4, ox = arow & 15;
    int oy = halfb * 8 + oyl;
    const float* Abase = g_h1p + (((size_t)bimg * 34 + 2 * oy) * 34 + 2 * ox) * 64 + ahalf * 16;
    const float* Bbase = g_w2 + (size_t)(n0 + brow) * 576 + bseg * 8;

    const int tapoff[9] = {0, 64, 128, 34 * 64, 34 * 64 + 64, 34 * 64 + 128,
                           68 * 64, 68 * 64 + 64, 68 * 64 + 128};

    float4 ra[4], rb[2];
#pragma unroll
    for (int j = 0; j < 4; j++) ra[j] = *(const float4*)(Abase + tapoff[0] + 4 * j);
#pragma unroll
    for (int j = 0; j < 2; j++) rb[j] = *(const float4*)(Bbase + 4 * j);

    // stage chunk 0 into buffer 0
    {
        float* Ab = Asm;
        float* Bb = Bsm;
#pragma unroll
        for (int j = 0; j < 4; j++) sts_tf32x4(&Ab[arow * 36 + ahalf * 16 + 4 * j], ra[j]);
#pragma unroll
        for (int j = 0; j < 2; j++) sts_tf32x4(&Bb[brow * 36 + bseg * 8 + 4 * j], rb[j]);
    }
    __syncthreads();

    for (int ch = 0; ch < 18; ch++) {
        int nb = ch & 1;
        if (ch + 1 < 18) {
            int c1 = ch + 1;
            const float* Ap = Abase + tapoff[c1 >> 1] + (c1 & 1) * 32;
            const float* Bp = Bbase + c1 * 32;
#pragma unroll
            for (int j = 0; j < 4; j++) ra[j] = *(const float4*)(Ap + 4 * j);
#pragma unroll
            for (int j = 0; j < 2; j++) rb[j] = *(const float4*)(Bp + 4 * j);
        }
        mma_chunk(Asm + nb * AS_STRIDE, Bsm + nb * BS_STRIDE, X);
        if (ch + 1 < 18) {
            float* Ab = Asm + (nb ^ 1) * AS_STRIDE;
            float* Bb = Bsm + (nb ^ 1) * BS_STRIDE;
#pragma unroll
            for (int j = 0; j < 4; j++) sts_tf32x4(&Ab[arow * 36 + ahalf * 16 + 4 * j], ra[j]);
#pragma unroll
            for (int j = 0; j < 2; j++) sts_tf32x4(&Bb[brow * 36 + bseg * 8 + 4 * j], rb[j]);
        }
        __syncthreads();
    }

    int m0 = bimg * 256 + halfb * 128;
    epilogue(X, g_h2n, m0, n0, 128, bias, 1);
}

// ---------------- generic tf32 GEMM (TN): C[m][n] = sum_k A[m][k]*B[n][k] -----
// Double-buffered. blockIdx.z = split-K chunk. Optional second pointer set for
// fused GRU (blockIdx.y >= ntile1 -> set 2).
__global__ void __launch_bounds__(256) gemm_mma(const float* __restrict__ A,
                                                const float* __restrict__ B,
                                                float* __restrict__ C,
                                                const float* __restrict__ A2,
                                                const float* __restrict__ B2,
                                                float* __restrict__ C2,
                                                int ntile1,
                                                int lda, int ldb, int ldc, int kLen,
                                                long long cStride,
                                                const float* __restrict__ bias, int act) {
    extern __shared__ float smem[];
    float* Asm = smem;
    float* Bsm = smem + 2 * AS_STRIDE;

    int tid = threadIdx.x;
    MmaCtx X;
    X.lane = tid & 31;
    int wid = tid >> 5;
    X.wm = wid & 3; X.wn = wid >> 2;
    X.gid = X.lane >> 2; X.tc = X.lane & 3;
#pragma unroll
    for (int mt = 0; mt < 2; mt++)
#pragma unroll
        for (int nt = 0; nt < 4; nt++)
#pragma unroll
            for (int i = 0; i < 4; i++) X.c[mt][nt][i] = 0.f;

    int ny = blockIdx.y;
    if (ny >= ntile1) { A = A2; B = B2; C = C2; ny -= ntile1; }
    int m0 = blockIdx.x << 7, n0 = ny << 6;
    long long k0 = (long long)blockIdx.z * kLen;

    int arow = tid >> 1, ahalf = tid & 1;
    int brow = tid >> 2, bseg = tid & 3;
    const float* Ap = A + (size_t)(m0 + arow) * lda + k0 + ahalf * 16;
    const float* Bp = B + (size_t)(n0 + brow) * ldb + k0 + bseg * 8;

    int nc = kLen >> 5;
    float4 ra[4], rb[2];
#pragma unroll
    for (int j = 0; j < 4; j++) ra[j] = *(const float4*)(Ap + 4 * j);
#pragma unroll
    for (int j = 0; j < 2; j++) rb[j] = *(const float4*)(Bp + 4 * j);

    {
#pragma unroll
        for (int j = 0; j < 4; j++) sts_tf32x4(&Asm[arow * 36 + ahalf * 16 + 4 * j], ra[j]);
#pragma unroll
        for (int j = 0; j < 2; j++) sts_tf32x4(&Bsm[brow * 36 + bseg * 8 + 4 * j], rb[j]);
    }
    __syncthreads();

    for (int ch = 0; ch < nc; ch++) {
        int nb = ch & 1;
        if (ch + 1 < nc) {
            Ap += 32; Bp += 32;
#pragma unroll
            for (int j = 0; j < 4; j++) ra[j] = *(const float4*)(Ap + 4 * j);
#pragma unroll
            for (int j = 0; j < 2; j++) rb[j] = *(const float4*)(Bp + 4 * j);
        }
        mma_chunk(Asm + nb * AS_STRIDE, Bsm + nb * BS_STRIDE, X);
        if (ch + 1 < nc) {
            float* Ab = Asm + (nb ^ 1) * AS_STRIDE;
            float* Bb = Bsm + (nb ^ 1) * BS_STRIDE;
#pragma unroll
            for (int j = 0; j < 4; j++) sts_tf32x4(&Ab[arow * 36 + ahalf * 16 + 4 * j], ra[j]);
#pragma unroll
            for (int j = 0; j < 2; j++) sts_tf32x4(&Bb[brow * 36 + bseg * 8 + 4 * j], rb[j]);
        }
        __syncthreads();
    }

    float* Cz = C + (long long)blockIdx.z * cStride;
    epilogue(X, Cz, m0, n0, ldc, bias, act);
}

// ---------------- split-K reduce + conv3 bias/leaky + prebox -> g_x -----------
__global__ void __launch_bounds__(256) build_x_kernel(const float* __restrict__ pre_box,
                                                      const float* __restrict__ pw,
                                                      const float* __restrict__ pb,
                                                      const float* __restrict__ c3b) {
    int t = blockIdx.x * 256 + threadIdx.x;
    int b = t >> 9, j = t & 511;
    float s;
    if (j < 256) {
        s = pb[j] + pre_box[b * 3] * pw[j * 3] + pre_box[b * 3 + 1] * pw[j * 3 + 1] +
            pre_box[b * 3 + 2] * pw[j * 3 + 2];
    } else {
        int n = j - 256;
        s = 0.f;
#pragma unroll
        for (int kz = 0; kz < 16; kz++) s += g_part[kz * 262144 + b * 256 + n];
        s += c3b[n];
        s = leaky(s);
    }
    g_x[t] = s;
}

// ---------------- GRU gates ----------------
__device__ __forceinline__ float sigmoid_t(float x) { return 0.5f + 0.5f * tanhf(0.5f * x); }

__global__ void __launch_bounds__(256) gates_kernel(const float* __restrict__ hh,
                                                    const float* __restrict__ bih,
                                                    const float* __restrict__ bhh,
                                                    float* __restrict__ out) {
    int t = blockIdx.x * 256 + threadIdx.x;
    int b = t >> 9, j = t & 511;
    size_t base = (size_t)b * 1536 + j;
    float ir = g_gi[base] + bih[j];
    float iz = g_gi[base + 512] + bih[512 + j];
    float inn = g_gi[base + 1024] + bih[1024 + j];
    float hr = g_gh[base] + bhh[j];
    float hz = g_gh[base + 512] + bhh[512 + j];
    float hn = g_gh[base + 1024] + bhh[1024 + j];
    float r = sigmoid_t(ir + hr);
    float z = sigmoid_t(iz + hz);
    float n = tanhf(inn + r * hn);
    float h0 = hh[t];
    float hnew = (1.f - z) * n + z * h0;
    out[t] = hnew;
    out[524288 + t] = hnew;
}

// ---------------- launch ----------------
extern "C" void kernel_launch(void* const* d_in, const int* in_sizes, int n_in,
                              void* d_out, int out_size) {
    (void)in_sizes; (void)n_in; (void)out_size;
    const float* pre_box = (const float*)d_in[0];
    const float* hm      = (const float*)d_in[1];
    const float* last_hh = (const float*)d_in[2];
    const float* pw      = (const float*)d_in[3];
    const float* pb      = (const float*)d_in[4];
    const float* c1w     = (const float*)d_in[5];
    const float* c1b     = (const float*)d_in[6];
    const float* c2w     = (const float*)d_in[7];
    const float* c2b     = (const float*)d_in[8];
    const float* c3w     = (const float*)d_in[9];
    const float* c3b     = (const float*)d_in[10];
    const float* wih     = (const float*)d_in[11];
    const float* whh     = (const float*)d_in[12];
    const float* bih     = (const float*)d_in[13];
    const float* bhh     = (const float*)d_in[14];
    float* out = (float*)d_out;

    float *p_h2n, *p_c3wp, *p_part, *p_x, *p_gi, *p_gh;
    cudaGetSymbolAddress((void**)&p_h2n, g_h2n);
    cudaGetSymbolAddress((void**)&p_c3wp, g_c3wp);
    cudaGetSymbolAddress((void**)&p_part, g_part);
    cudaGetSymbolAddress((void**)&p_x, g_x);
    cudaGetSymbolAddress((void**)&p_gi, g_gi);
    cudaGetSymbolAddress((void**)&p_gh, g_gh);

    cudaFuncSetAttribute(conv2_mma, cudaFuncAttributeMaxDynamicSharedMemorySize, SMEM_BYTES);
    cudaFuncSetAttribute(gemm_mma, cudaFuncAttributeMaxDynamicSharedMemorySize, SMEM_BYTES);

    conv1_kernel<<<4096, 256>>>(hm, c1w, c1b);
    w2p_kernel<<<288, 256>>>(c2w);
    c3t_kernel<<<dim3(8, 4, 256), dim3(32, 8)>>>(c3w);

    // conv2 implicit GEMM: reads g_h1p, writes NHWC g_h2n, bias+leaky fused
    conv2_mma<<<dim3(2048, 2, 1), 256, SMEM_BYTES>>>(c2b);

    // conv3: M=1024, N=256, K=32768, split-K 16
    gemm_mma<<<dim3(8, 4, 16), 256, SMEM_BYTES>>>(p_h2n, p_c3wp, p_part,
                                                  (const float*)0, (const float*)0, (float*)0,
                                                  1 << 30, 32768, 32768, 256, 2048, 262144LL,
                                                  (const float*)0, 0);
    build_x_kernel<<<2048, 256>>>(pre_box, pw, pb, c3b);

    // fused GRU GEMMs: y<24 -> gi = x@wih^T, y>=24 -> gh = hh@whh^T
    gemm_mma<<<dim3(8, 48, 1), 256, SMEM_BYTES>>>(p_x, wih, p_gi,
                                                  last_hh, whh, p_gh,
                                                  24, 512, 512, 1536, 512, 0LL,
                                                  (const float*)0, 0);

    gates_kernel<<<2048, 256>>>(last_hh, bih, bhh, out);
}

// round 7
// speedup vs baseline: 3.4773x; 1.7377x over previous
#include <cuda_runtime.h>
#include <cuda_fp16.h>
#include <math.h>
#include <stdint.h>

// B=1024, H=512. conv1 2->64 3x3 s1p1 (32x32), conv2 64->128 3x3 s2p1 (->16x16),
// conv3 128->256 16x16 valid (->1x1), GRU 512.  fp16 tensor-core path (f32 accum).
#define LEAK 0.01f

// ---------------- device scratch ----------------
// g_h1p: padded NHWC conv1 output [b][34][34][64] fp16; borders never written ->
// stay zero (the padding conv2 needs).
__device__ __half g_h1p[1024ull * 34 * 34 * 64];   // ~151MB
__device__ __half g_w2h[128 * 576];                // conv2 weights [oc][tap*64+ic]
__device__ __half g_h2n[1024ull * 256 * 128];      // conv2 out NHWC fp16 (~67MB)
__device__ __half g_c3wp[256ull * 32768];          // conv3 weights [n][p*128+oc]
__device__ __half g_xh[1024 * 512];                // GRU input fp16
__device__ __half g_hh16[1024 * 512];              // last_hh fp16
__device__ __half g_wih16[1536 * 512];
__device__ __half g_whh16[1536 * 512];
__device__ float g_part[16ull * 1024 * 256];       // conv3 split-K partials (f32)
__device__ float g_gi[1024 * 1536];
__device__ float g_gh[1024 * 1536];

__device__ __forceinline__ float leaky(float v) { return v >= 0.f ? v : LEAK * v; }

// ---------------- conv1: 2->64 3x3 p1 + leaky -> padded NHWC fp16 -------------
__global__ void __launch_bounds__(256) conv1_kernel(const float* __restrict__ hm,
                                                    const float* __restrict__ w,
                                                    const float* __restrict__ bias) {
    __shared__ float in_s[2048];
    __shared__ float w_s[64 * 20];
    __shared__ float b_s[64];
    int b = blockIdx.x >> 2, q = blockIdx.x & 3;
    int tid = threadIdx.x;
    int yl = tid >> 5, x = tid & 31;
    int y = q * 8 + yl;

    const float4* src = (const float4*)(hm + (size_t)b * 2048);
    for (int i = tid; i < 512; i += 256) ((float4*)in_s)[i] = src[i];
    for (int i = tid; i < 1280; i += 256) {
        int oc = i / 20, k = i - oc * 20;
        w_s[i] = (k < 18) ? w[oc * 18 + k] : 0.f;
    }
    if (tid < 64) b_s[tid] = bias[tid];
    __syncthreads();

    float v[18];
#pragma unroll
    for (int c = 0; c < 2; c++)
#pragma unroll
        for (int ky = 0; ky < 3; ky++)
#pragma unroll
            for (int kx = 0; kx < 3; kx++) {
                int yy = y - 1 + ky, xx = x - 1 + kx;
                float t = 0.f;
                if (yy >= 0 && yy < 32 && xx >= 0 && xx < 32) t = in_s[c * 1024 + yy * 32 + xx];
                v[c * 9 + ky * 3 + kx] = t;
            }

    __half* dst = g_h1p + (((size_t)b * 34 + y + 1) * 34 + x + 1) * 64;
#pragma unroll 2
    for (int o8 = 0; o8 < 8; o8++) {
        __half2 hp[4];
#pragma unroll
        for (int u = 0; u < 4; u++) {
            float pr[2];
#pragma unroll
            for (int g = 0; g < 2; g++) {
                int oc = o8 * 8 + u * 2 + g;
                const float4* wp = (const float4*)(w_s + oc * 20);
                float4 w0 = wp[0], w1 = wp[1], w2 = wp[2], w3 = wp[3];
                float2 w4 = *(const float2*)(w_s + oc * 20 + 16);
                float acc = b_s[oc];
                acc += v[0] * w0.x + v[1] * w0.y + v[2] * w0.z + v[3] * w0.w;
                acc += v[4] * w1.x + v[5] * w1.y + v[6] * w1.z + v[7] * w1.w;
                acc += v[8] * w2.x + v[9] * w2.y + v[10] * w2.z + v[11] * w2.w;
                acc += v[12] * w3.x + v[13] * w3.y + v[14] * w3.z + v[15] * w3.w;
                acc += v[16] * w4.x + v[17] * w4.y;
                pr[g] = leaky(acc);
            }
            hp[u] = __floats2half2_rn(pr[0], pr[1]);
        }
        ((uint4*)dst)[o8] = *(uint4*)hp;
    }
}

// ---------------- weight prep ----------------
__global__ void __launch_bounds__(256) w2p_kernel(const float* __restrict__ w) {
    int t = blockIdx.x * 256 + threadIdx.x;
    if (t >= 128 * 576) return;
    int oc = t / 576, k = t - oc * 576;
    int tap = k >> 6, ic = k & 63;
    g_w2h[t] = __float2half(w[oc * 576 + ic * 9 + tap]);
}

__global__ void c3t_kernel(const float* __restrict__ w) {
    __shared__ float t[32][33];
    int n = blockIdx.z, oc0 = blockIdx.y * 32, p0 = blockIdx.x * 32;
    int tx = threadIdx.x, ty = threadIdx.y;
#pragma unroll
    for (int rr = 0; rr < 4; rr++)
        t[ty + rr * 8][tx] = w[(size_t)n * 32768 + (size_t)(oc0 + ty + rr * 8) * 256 + p0 + tx];
    __syncthreads();
#pragma unroll
    for (int rr = 0; rr < 4; rr++)
        g_c3wp[(size_t)n * 32768 + (size_t)(p0 + ty + rr * 8) * 128 + oc0 + tx] =
            __float2half(t[tx][ty + rr * 8]);
}

__global__ void __launch_bounds__(256) cvt16_kernel(const float* __restrict__ src,
                                                    __half* __restrict__ dst, int n2) {
    int i = blockIdx.x * 256 + threadIdx.x;
    if (i >= n2) return;
    float2 v = ((const float2*)src)[i];
    ((__half2*)dst)[i] = __floats2half2_rn(v.x, v.y);
}

// ================= fp16 m16n8k16 MMA micro-kernel =================
// CTA tile 128x64, 8 warps (4m x 2n), warp tile 32x32. Smem rows: 72 halves
// (144B) stride -> fragment LDS.32 bank = (4*gid+tc)%32, conflict-free.
#define AS_H 9216   // 128*72 halves
#define BS_H 4608   // 64*72
#define SMEM_BYTES ((2 * (AS_H + BS_H)) * 2)

struct MmaCtx {
    int wm, wn, gid, tc;
    float c[2][4][4];
};

__device__ __forceinline__ void mma_chunk(const __half* As, const __half* Bs, MmaCtx& X) {
#pragma unroll
    for (int ks = 0; ks < 4; ks++) {
        uint32_t a[2][4], bq[4][2];
#pragma unroll
        for (int mt = 0; mt < 2; mt++) {
            const __half* ap = &As[(X.wm * 32 + mt * 16 + X.gid) * 72 + ks * 16 + X.tc * 2];
            a[mt][0] = *(const uint32_t*)ap;
            a[mt][1] = *(const uint32_t*)(ap + 8 * 72);
            a[mt][2] = *(const uint32_t*)(ap + 8);
            a[mt][3] = *(const uint32_t*)(ap + 8 * 72 + 8);
        }
#pragma unroll
        for (int nt = 0; nt < 4; nt++) {
            const __half* bp = &Bs[(X.wn * 32 + nt * 8 + X.gid) * 72 + ks * 16 + X.tc * 2];
            bq[nt][0] = *(const uint32_t*)bp;
            bq[nt][1] = *(const uint32_t*)(bp + 8);
        }
#pragma unroll
        for (int mt = 0; mt < 2; mt++)
#pragma unroll
            for (int nt = 0; nt < 4; nt++) {
                asm volatile(
                    "mma.sync.aligned.m16n8k16.row.col.f32.f16.f16.f32 "
                    "{%0,%1,%2,%3}, {%4,%5,%6,%7}, {%8,%9}, {%0,%1,%2,%3};"
                    : "+f"(X.c[mt][nt][0]), "+f"(X.c[mt][nt][1]),
                      "+f"(X.c[mt][nt][2]), "+f"(X.c[mt][nt][3])
                    : "r"(a[mt][0]), "r"(a[mt][1]), "r"(a[mt][2]), "r"(a[mt][3]),
                      "r"(bq[nt][0]), "r"(bq[nt][1]));
            }
    }
}

// f32 epilogue (C float) or fp16 epilogue (C half), bias+act optional
__device__ __forceinline__ void epilogue_f32(MmaCtx& X, float* Cz, int m0, int n0, int ldc) {
#pragma unroll
    for (int mt = 0; mt < 2; mt++) {
        int r0 = m0 + X.wm * 32 + mt * 16 + X.gid;
#pragma unroll
        for (int nt = 0; nt < 4; nt++) {
            int col = n0 + X.wn * 32 + nt * 8 + 2 * X.tc;
            *(float2*)(Cz + (size_t)r0 * ldc + col) = make_float2(X.c[mt][nt][0], X.c[mt][nt][1]);
            *(float2*)(Cz + (size_t)(r0 + 8) * ldc + col) = make_float2(X.c[mt][nt][2], X.c[mt][nt][3]);
        }
    }
}

// ---------------- conv2 implicit GEMM: M=262144 N=128 K=576 (9 taps) ----------
__global__ void __launch_bounds__(256) conv2_mma(const float* __restrict__ bias) {
    extern __shared__ __half smem[];
    __half* Asm = smem;
    __half* Bsm = smem + 2 * AS_H;

    int tid = threadIdx.x;
    MmaCtx X;
    int lane = tid & 31, wid = tid >> 5;
    X.wm = wid & 3; X.wn = wid >> 2;
    X.gid = lane >> 2; X.tc = lane & 3;
#pragma unroll
    for (int mt = 0; mt < 2; mt++)
#pragma unroll
        for (int nt = 0; nt < 4; nt++)
#pragma unroll
            for (int i = 0; i < 4; i++) X.c[mt][nt][i] = 0.f;

    int bimg = blockIdx.x >> 1, halfb = blockIdx.x & 1;
    int n0 = blockIdx.y << 6;

    // A: 128 rows x 64 halves/chunk; thread: row=tid>>1, 32 halves (4 x uint4)
    int arow = tid >> 1, ahalf = tid & 1;
    // B: 64 rows x 64 halves; thread: row=tid>>2, 16 halves (2 x uint4)
    int brow = tid >> 2, bseg = tid & 3;

    int oyl = arow >> 4, ox = arow & 15;
    int oy = halfb * 8 + oyl;
    const __half* Abase = g_h1p + (((size_t)bimg * 34 + 2 * oy) * 34 + 2 * ox) * 64 + ahalf * 32;
    const __half* Bbase = g_w2h + (size_t)(n0 + brow) * 576 + bseg * 16;

    const int tapoff[9] = {0, 64, 128, 34 * 64, 34 * 64 + 64, 34 * 64 + 128,
                           68 * 64, 68 * 64 + 64, 68 * 64 + 128};

    uint4 ra[4], rb[2];
#pragma unroll
    for (int j = 0; j < 4; j++) ra[j] = ((const uint4*)(Abase + tapoff[0]))[j];
#pragma unroll
    for (int j = 0; j < 2; j++) rb[j] = ((const uint4*)Bbase)[j];

    uint32_t asts = arow * 72 + ahalf * 32;
    uint32_t bsts = brow * 72 + bseg * 16;
    {
#pragma unroll
        for (int j = 0; j < 4; j++) *(uint4*)&Asm[asts + 8 * j] = ra[j];
#pragma unroll
        for (int j = 0; j < 2; j++) *(uint4*)&Bsm[bsts + 8 * j] = rb[j];
    }
    __syncthreads();

    for (int ch = 0; ch < 9; ch++) {
        int nb = ch & 1;
        if (ch + 1 < 9) {
            const __half* Ap = Abase + tapoff[ch + 1];
            const __half* Bp = Bbase + (ch + 1) * 64;
#pragma unroll
            for (int j = 0; j < 4; j++) ra[j] = ((const uint4*)Ap)[j];
#pragma unroll
            for (int j = 0; j < 2; j++) rb[j] = ((const uint4*)Bp)[j];
        }
        mma_chunk(Asm + nb * AS_H, Bsm + nb * BS_H, X);
        if (ch + 1 < 9) {
            __half* Ab = Asm + (nb ^ 1) * AS_H;
            __half* Bb = Bsm + (nb ^ 1) * BS_H;
#pragma unroll
            for (int j = 0; j < 4; j++) *(uint4*)&Ab[asts + 8 * j] = ra[j];
#pragma unroll
            for (int j = 0; j < 2; j++) *(uint4*)&Bb[bsts + 8 * j] = rb[j];
        }
        __syncthreads();
    }

    // epilogue: bias + leaky, write fp16 NHWC
    int m0 = bimg * 256 + halfb * 128;
#pragma unroll
    for (int mt = 0; mt < 2; mt++) {
        int r0 = m0 + X.wm * 32 + mt * 16 + X.gid;
#pragma unroll
        for (int nt = 0; nt < 4; nt++) {
            int col = n0 + X.wn * 32 + nt * 8 + 2 * X.tc;
            float b0 = bias[col], b1 = bias[col + 1];
            float v0 = leaky(X.c[mt][nt][0] + b0), v1 = leaky(X.c[mt][nt][1] + b1);
            float v2 = leaky(X.c[mt][nt][2] + b0), v3 = leaky(X.c[mt][nt][3] + b1);
            *(__half2*)(g_h2n + (size_t)r0 * 128 + col) = __floats2half2_rn(v0, v1);
            *(__half2*)(g_h2n + (size_t)(r0 + 8) * 128 + col) = __floats2half2_rn(v2, v3);
        }
    }
}

// ---------------- generic fp16 GEMM (TN): C[m][n] = sum_k A[m][k]*B[n][k] -----
// blockIdx.z = split-K chunk; optional second pointer set (fused GRU).
__global__ void __launch_bounds__(256) gemm_mma(const __half* __restrict__ A,
                                                const __half* __restrict__ B,
                                                float* __restrict__ C,
                                                const __half* __restrict__ A2,
                                                const __half* __restrict__ B2,
                                                float* __restrict__ C2,
                                                int ntile1,
                                                int lda, int ldb, int ldc, int kLen,
                                                long long cStride) {
    extern __shared__ __half smem[];
    __half* Asm = smem;
    __half* Bsm = smem + 2 * AS_H;

    int tid = threadIdx.x;
    MmaCtx X;
    int lane = tid & 31, wid = tid >> 5;
    X.wm = wid & 3; X.wn = wid >> 2;
    X.gid = lane >> 2; X.tc = lane & 3;
#pragma unroll
    for (int mt = 0; mt < 2; mt++)
#pragma unroll
        for (int nt = 0; nt < 4; nt++)
#pragma unroll
            for (int i = 0; i < 4; i++) X.c[mt][nt][i] = 0.f;

    int ny = blockIdx.y;
    if (ny >= ntile1) { A = A2; B = B2; C = C2; ny -= ntile1; }
    int m0 = blockIdx.x << 7, n0 = ny << 6;
    long long k0 = (long long)blockIdx.z * kLen;

    int arow = tid >> 1, ahalf = tid & 1;
    int brow = tid >> 2, bseg = tid & 3;
    const __half* Ap = A + (size_t)(m0 + arow) * lda + k0 + ahalf * 32;
    const __half* Bp = B + (size_t)(n0 + brow) * ldb + k0 + bseg * 16;

    int nc = kLen >> 6;
    uint4 ra[4], rb[2];
#pragma unroll
    for (int j = 0; j < 4; j++) ra[j] = ((const uint4*)Ap)[j];
#pragma unroll
    for (int j = 0; j < 2; j++) rb[j] = ((const uint4*)Bp)[j];

    uint32_t asts = arow * 72 + ahalf * 32;
    uint32_t bsts = brow * 72 + bseg * 16;
    {
#pragma unroll
        for (int j = 0; j < 4; j++) *(uint4*)&Asm[asts + 8 * j] = ra[j];
#pragma unroll
        for (int j = 0; j < 2; j++) *(uint4*)&Bsm[bsts + 8 * j] = rb[j];
    }
    __syncthreads();

    for (int ch = 0; ch < nc; ch++) {
        int nb = ch & 1;
        if (ch + 1 < nc) {
            Ap += 64; Bp += 64;
#pragma unroll
            for (int j = 0; j < 4; j++) ra[j] = ((const uint4*)Ap)[j];
#pragma unroll
            for (int j = 0; j < 2; j++) rb[j] = ((const uint4*)Bp)[j];
        }
        mma_chunk(Asm + nb * AS_H, Bsm + nb * BS_H, X);
        if (ch + 1 < nc) {
            __half* Ab = Asm + (nb ^ 1) * AS_H;
            __half* Bb = Bsm + (nb ^ 1) * BS_H;
#pragma unroll
            for (int j = 0; j < 4; j++) *(uint4*)&Ab[asts + 8 * j] = ra[j];
#pragma unroll
            for (int j = 0; j < 2; j++) *(uint4*)&Bb[bsts + 8 * j] = rb[j];
        }
        __syncthreads();
    }

    float* Cz = C + (long long)blockIdx.z * cStride;
    epilogue_f32(X, Cz, m0, n0, ldc);
}

// ---------------- split-K reduce + conv3 bias/leaky + prebox -> g_xh ----------
__global__ void __launch_bounds__(256) build_x_kernel(const float* __restrict__ pre_box,
                                                      const float* __restrict__ pw,
                                                      const float* __restrict__ pb,
                                                      const float* __restrict__ c3b) {
    int t = blockIdx.x * 256 + threadIdx.x;
    int b = t >> 9, j = t & 511;
    float s;
    if (j < 256) {
        s = pb[j] + pre_box[b * 3] * pw[j * 3] + pre_box[b * 3 + 1] * pw[j * 3 + 1] +
            pre_box[b * 3 + 2] * pw[j * 3 + 2];
    } else {
        int n = j - 256;
        s = 0.f;
#pragma unroll
        for (int kz = 0; kz < 16; kz++) s += g_part[kz * 262144 + b * 256 + n];
        s += c3b[n];
        s = leaky(s);
    }
    g_xh[t] = __float2half(s);
}

// ---------------- GRU gates ----------------
__device__ __forceinline__ float sigmoid_t(float x) { return 0.5f + 0.5f * tanhf(0.5f * x); }

__global__ void __launch_bounds__(256) gates_kernel(const float* __restrict__ hh,
                                                    const float* __restrict__ bih,
                                                    const float* __restrict__ bhh,
                                                    float* __restrict__ out) {
    int t = blockIdx.x * 256 + threadIdx.x;
    int b = t >> 9, j = t & 511;
    size_t base = (size_t)b * 1536 + j;
    float ir = g_gi[base] + bih[j];
    float iz = g_gi[base + 512] + bih[512 + j];
    float inn = g_gi[base + 1024] + bih[1024 + j];
    float hr = g_gh[base] + bhh[j];
    float hz = g_gh[base + 512] + bhh[512 + j];
    float hn = g_gh[base + 1024] + bhh[1024 + j];
    float r = sigmoid_t(ir + hr);
    float z = sigmoid_t(iz + hz);
    float n = tanhf(inn + r * hn);
    float h0 = hh[t];
    float hnew = (1.f - z) * n + z * h0;
    out[t] = hnew;
    out[524288 + t] = hnew;
}

// ---------------- launch ----------------
extern "C" void kernel_launch(void* const* d_in, const int* in_sizes, int n_in,
                              void* d_out, int out_size) {
    (void)in_sizes; (void)n_in; (void)out_size;
    const float* pre_box = (const float*)d_in[0];
    const float* hm      = (const float*)d_in[1];
    const float* last_hh = (const float*)d_in[2];
    const float* pw      = (const float*)d_in[3];
    const float* pb      = (const float*)d_in[4];
    const float* c1w     = (const float*)d_in[5];
    const float* c1b     = (const float*)d_in[6];
    const float* c2w     = (const float*)d_in[7];
    const float* c2b     = (const float*)d_in[8];
    const float* c3w     = (const float*)d_in[9];
    const float* c3b     = (const float*)d_in[10];
    const float* wih     = (const float*)d_in[11];
    const float* whh     = (const float*)d_in[12];
    const float* bih     = (const float*)d_in[13];
    const float* bhh     = (const float*)d_in[14];
    float* out = (float*)d_out;

    __half *p_h2n, *p_c3wp, *p_xh, *p_hh16, *p_wih16, *p_whh16;
    float *p_part, *p_gi, *p_gh;
    cudaGetSymbolAddress((void**)&p_h2n, g_h2n);
    cudaGetSymbolAddress((void**)&p_c3wp, g_c3wp);
    cudaGetSymbolAddress((void**)&p_xh, g_xh);
    cudaGetSymbolAddress((void**)&p_hh16, g_hh16);
    cudaGetSymbolAddress((void**)&p_wih16, g_wih16);
    cudaGetSymbolAddress((void**)&p_whh16, g_whh16);
    cudaGetSymbolAddress((void**)&p_part, g_part);
    cudaGetSymbolAddress((void**)&p_gi, g_gi);
    cudaGetSymbolAddress((void**)&p_gh, g_gh);

    cudaFuncSetAttribute(conv2_mma, cudaFuncAttributeMaxDynamicSharedMemorySize, SMEM_BYTES);
    cudaFuncSetAttribute(gemm_mma, cudaFuncAttributeMaxDynamicSharedMemorySize, SMEM_BYTES);

    conv1_kernel<<<4096, 256>>>(hm, c1w, c1b);
    w2p_kernel<<<288, 256>>>(c2w);
    c3t_kernel<<<dim3(8, 4, 256), dim3(32, 8)>>>(c3w);
    cvt16_kernel<<<1536, 256>>>(wih, p_wih16, 393216);
    cvt16_kernel<<<1536, 256>>>(whh, p_whh16, 393216);
    cvt16_kernel<<<1024, 256>>>(last_hh, p_hh16, 262144);

    // conv2 implicit GEMM: reads g_h1p fp16, writes fp16 NHWC g_h2n
    conv2_mma<<<dim3(2048, 2, 1), 256, SMEM_BYTES>>>(c2b);

    // conv3: M=1024, N=256, K=32768, split-K 16
    gemm_mma<<<dim3(8, 4, 16), 256, SMEM_BYTES>>>(p_h2n, p_c3wp, p_part,
                                                  (const __half*)0, (const __half*)0, (float*)0,
                                                  1 << 30, 32768, 32768, 256, 2048, 262144LL);
    build_x_kernel<<<2048, 256>>>(pre_box, pw, pb, c3b);

    // fused GRU GEMMs: y<24 -> gi = x@wih^T, y>=24 -> gh = hh@whh^T
    gemm_mma<<<dim3(8, 48, 1), 256, SMEM_BYTES>>>(p_xh, p_wih16, p_gi,
                                                  p_hh16, p_whh16, p_gh,
                                                  24, 512, 512, 1536, 512, 0LL);

    gates_kernel<<<2048, 256>>>(last_hh, bih, bhh, out);
}